// round 4
// baseline (speedup 1.0000x reference)
#include <cuda_runtime.h>
#include <cstdint>
#include <float.h>
#include <math.h>

// Problem constants (fixed by the dataset)
#define TT 64
#define UU 142
#define II 4500
#define BB 16384
#define KK 10

#define NPER 5                 // lane-major: lane owns users v = 5*lane + j
#define FULL_MASK 0xFFFFFFFFu

#define NWARPS 4096            // 512 blocks x 8 warps
#define ROWS_PER_WARP 4        // 16384 / 4096

// order-preserving float->uint map (monotone increasing); 0 reserved as
// "invalid/selected" sentinel (all real keys for sim in [-1,1] are > 0)
__device__ __forceinline__ unsigned f2ord(float f) {
    unsigned b = __float_as_uint(f);
    return (b & 0x80000000u) ? ~b : (b | 0x80000000u);
}

__global__ __launch_bounds__(256)
void ucf_kernel(const float* __restrict__ qos,      // (T,U,I)
                const float* __restrict__ uavg,     // (T,U)
                const float* __restrict__ sim,      // (U,U)
                const int*   __restrict__ user_id,  // (B,)
                const int*   __restrict__ item_id,  // (B,)
                const int*   __restrict__ time_id,  // (B,)
                float*       __restrict__ out)      // (B,)
{
    const int gwarp = (blockIdx.x * blockDim.x + threadIdx.x) >> 5;
    const int lane  = threadIdx.x & 31;
    const int vbase = lane * NPER;

    // ---- pipeline prologue: issue gathers for row 0 ----
    int u, t;
    float qv[NPER], sv[NPER];
    {
        const int r = gwarp;                       // row for iteration 0
        u = __ldg(user_id + r);
        const int i = __ldg(item_id + r);
        t = __ldg(time_id + r);
        const float* __restrict__ qb = qos + (size_t)t * (UU * II) + i;
        const float* __restrict__ sr = sim + (size_t)u * UU;
        #pragma unroll
        for (int j = 0; j < NPER; j++) {
            const int v = vbase + j;
            const bool ok = (v < UU);
            qv[j] = ok ? __ldg(qb + (size_t)v * II) : 0.0f;
            sv[j] = ok ? __ldg(sr + v) : 0.0f;
        }
    }

    #pragma unroll
    for (int it = 0; it < ROWS_PER_WARP; it++) {
        const int rcur = gwarp + it * NWARPS;
        const int tcur = u >= 0 ? t : t;           // keep current t,u
        const int ucur = u;

        // ---- prefetch NEXT row's gathers (independent, overlaps the top-K
        //      below which consumes the CURRENT row's in-flight loads) ----
        float qn[NPER], sn[NPER];
        int un = 0, tn = 0;
        if (it + 1 < ROWS_PER_WARP) {
            const int rn = gwarp + (it + 1) * NWARPS;
            un = __ldg(user_id + rn);
            const int in_ = __ldg(item_id + rn);
            tn = __ldg(time_id + rn);
            const float* __restrict__ qb = qos + (size_t)tn * (UU * II) + in_;
            const float* __restrict__ sr = sim + (size_t)un * UU;
            #pragma unroll
            for (int j = 0; j < NPER; j++) {
                const int v = vbase + j;
                const bool ok = (v < UU);
                qn[j] = ok ? __ldg(qb + (size_t)v * II) : 0.0f;
                sn[j] = ok ? __ldg(sr + v) : 0.0f;
            }
        } else {
            #pragma unroll
            for (int j = 0; j < NPER; j++) { qn[j] = 0.0f; sn[j] = 0.0f; }
        }

        // ---- consume current row ----
        float    rval[NPER];
        float    sval[NPER];
        unsigned ordu[NPER];
        #pragma unroll
        for (int j = 0; j < NPER; j++) {
            const int v = vbase + j;
            const bool ok = (v < UU);
            const float q = qv[j];
            const float s = (ok && q > 0.0f) ? sv[j] : 0.0f;
            rval[j] = q;
            sval[j] = s;
            ordu[j] = ok ? f2ord(s) : 0u;          // invalid -> sentinel 0
        }

        // iterative top-K via redux.max + ballot; tie-break lowest global
        // index (lane-major => lowest lane, strict '>' scan => lowest j)
        unsigned selmask = 0;
        float Spart = 0.0f;
        #pragma unroll
        for (int k = 0; k < KK; k++) {
            unsigned bestord = 0u;
            int bestj = 0;
            #pragma unroll
            for (int j = 0; j < NPER; j++)
                if (ordu[j] > bestord) { bestord = ordu[j]; bestj = j; }
            const unsigned maxord  = __reduce_max_sync(FULL_MASK, bestord);
            const unsigned winners = __ballot_sync(FULL_MASK, bestord == maxord);
            const int winner = __ffs(winners) - 1;
            if (lane == winner) {
                #pragma unroll
                for (int j = 0; j < NPER; j++) {
                    if (j == bestj) {
                        Spart += sval[j];
                        ordu[j] = 0u;
                        selmask |= 1u << j;
                    }
                }
            }
        }

        float S = Spart;
        #pragma unroll
        for (int off = 16; off > 0; off >>= 1)
            S += __shfl_xor_sync(FULL_MASK, S, off);
        const float denom = S + 1e-8f;

        const float* __restrict__ arow = uavg + (size_t)tcur * UU;
        float acc = 0.0f;
        #pragma unroll
        for (int j = 0; j < NPER; j++) {
            if ((selmask >> j) & 1u) {
                const int v = vbase + j;
                float w = sval[j] / denom;
                if (isnan(w))      w = 0.0f;
                else if (isinf(w)) w = copysignf(3.4028234663852886e38f, w);
                acc += w * (rval[j] - __ldg(arow + v));
            }
        }
        #pragma unroll
        for (int off = 16; off > 0; off >>= 1)
            acc += __shfl_xor_sync(FULL_MASK, acc, off);

        if (lane == 0)
            out[rcur] = __ldg(arow + ucur) + acc;

        // ---- rotate pipeline buffers ----
        u = un; t = tn;
        #pragma unroll
        for (int j = 0; j < NPER; j++) { qv[j] = qn[j]; sv[j] = sn[j]; }
    }
}

extern "C" void kernel_launch(void* const* d_in, const int* in_sizes, int n_in,
                              void* d_out, int out_size)
{
    const float* qos   = (const float*)d_in[0];  // (64,142,4500)
    const float* uavg  = (const float*)d_in[1];  // (64,142)
    const float* sim   = (const float*)d_in[2];  // (142,142)
    const int*   uid   = (const int*)  d_in[3];  // (16384,)
    const int*   iid   = (const int*)  d_in[4];  // (16384,)
    const int*   tid   = (const int*)  d_in[5];  // (16384,)
    float*       out   = (float*)d_out;          // (16384,)

    const int threads = 256;                       // 8 warps/block
    const int blocks  = (NWARPS * 32) / threads;   // 512
    ucf_kernel<<<blocks, threads>>>(qos, uavg, sim, uid, iid, tid, out);
}